// round 2
// baseline (speedup 1.0000x reference)
#include <cuda_runtime.h>
#include <cstdint>
#include <cstddef>

#define D_FEAT    128
#define N_STEPS   256          // O_SIZE: only first 256 scan steps feed the output
#define N_NEURONS 1024
#define W_TILE    (D_FEAT * D_FEAT)           // 16384 floats = 64 KB per step
#define NBUF      3

// smem layout (floats): Wbuf[3] | vbuf 128 | part 1024 | acoef 256 | mbars
#define SMF_VBUF   (NBUF * W_TILE)
#define SMF_PART   (SMF_VBUF + 128)
#define SMF_ACOEF  (SMF_PART + 1024)
#define SMF_MBAR   (SMF_ACOEF + 256)          // 8-byte aligned (index*4 % 8 == 0)
#define SMEM_FLOATS (SMF_MBAR + 8)
#define SMEM_BYTES  (SMEM_FLOATS * 4)

// Scratch: u_t vectors produced by the chain, consumed by the output CTAs.
__device__ __align__(16) float g_u[N_STEPS * D_FEAT];
__device__ int g_flag[N_STEPS];   // zero-init; set (never cleared) by chain CTA

// ---------------- PTX helpers ----------------
__device__ __forceinline__ unsigned smem_u32(const void* p) {
    unsigned r;
    asm("{ .reg .u64 t; cvta.to.shared.u64 t, %1; cvt.u32.u64 %0, t; }" : "=r"(r) : "l"(p));
    return r;
}
__device__ __forceinline__ void mbar_init(unsigned m, unsigned cnt) {
    asm volatile("mbarrier.init.shared.b64 [%0], %1;" :: "r"(m), "r"(cnt) : "memory");
}
__device__ __forceinline__ void mbar_expect_tx(unsigned m, unsigned bytes) {
    asm volatile("mbarrier.arrive.expect_tx.shared.b64 _, [%0], %1;" :: "r"(m), "r"(bytes) : "memory");
}
__device__ __forceinline__ void mbar_wait(unsigned m, unsigned parity) {
    asm volatile(
        "{\n\t"
        ".reg .pred P1;\n\t"
        "WL_%=:\n\t"
        "mbarrier.try_wait.parity.acquire.cta.shared::cta.b64 P1, [%0], %1, 0x989680;\n\t"
        "@P1 bra.uni WD_%=;\n\t"
        "bra.uni WL_%=;\n\t"
        "WD_%=:\n\t"
        "}"
        :: "r"(m), "r"(parity) : "memory");
}
__device__ __forceinline__ void tma_1d(unsigned dst, const void* src, unsigned bytes, unsigned m) {
    asm volatile(
        "cp.async.bulk.shared::cta.global.mbarrier::complete_tx::bytes [%0], [%1], %2, [%3];"
        :: "r"(dst), "l"(src), "r"(bytes), "r"(m) : "memory");
}
__device__ __forceinline__ float tanha(float v) {
    float r;
    asm("tanh.approx.f32 %0, %1;" : "=f"(r) : "f"(v));
    return r;
}
__device__ __forceinline__ void flag_release(int t) {
    __threadfence();
    asm volatile("st.global.release.gpu.b32 [%0], %1;" :: "l"(&g_flag[t]), "r"(1) : "memory");
}
__device__ __forceinline__ int flag_acquire(int t) {
    int f;
    asm volatile("ld.global.acquire.gpu.b32 %0, [%1];" : "=r"(f) : "l"(&g_flag[t]) : "memory");
    return f;
}

// One chain step. RC holds W_t in registers; loads W_{t+1} into RN (overlapped
// with FFMAs + serial tail). vbuf holds v_t on entry, v_{t+1} on exit.
#define CHAIN_STEP(RC, RN, t) do {                                                   \
    if ((t) < N_STEPS - 1) {                                                         \
        const int nb = ((t) + 1) % NBUF;                                             \
        mbar_wait(mbar_base + 8u * nb, (((t) + 1) / NBUF) & 1);                      \
        const float4* Wn = (const float4*)(sm + nb * W_TILE);                        \
        _Pragma("unroll")                                                            \
        for (int r = 0; r < 16; r++) RN[r] = Wn[((r << 3) + w) * 32 + lane];         \
    }                                                                                \
    float4 acc = make_float4(0.f, 0.f, 0.f, 0.f);                                    \
    _Pragma("unroll")                                                                \
    for (int r = 0; r < 16; r++) {                                                   \
        const float vj = vbuf[(r << 3) + w];                                         \
        acc.x += vj * RC[r].x; acc.y += vj * RC[r].y;                                \
        acc.z += vj * RC[r].z; acc.w += vj * RC[r].w;                                \
    }                                                                                \
    ((float4*)part)[(w << 5) + lane] = acc;                                          \
    __syncthreads();                                                                 \
    if (tid == 0 && (t) + NBUF < N_STEPS) {                                          \
        const unsigned mb = mbar_base + 8u * ((t) % NBUF);                           \
        mbar_expect_tx(mb, W_TILE * 4);                                              \
        tma_1d(smem_u32(sm + ((t) % NBUF) * W_TILE),                                 \
               W + (size_t)((t) + NBUF) * W_TILE, W_TILE * 4, mb);                   \
    }                                                                                \
    if (tid < 128) {                                                                 \
        float u = part[tid]       + part[128 + tid] + part[256 + tid]                \
                + part[384 + tid] + part[512 + tid] + part[640 + tid]                \
                + part[768 + tid] + part[896 + tid];                                 \
        __stcg(&g_u[(t) * 128 + tid], u);                                            \
        if ((t) < N_STEPS - 1) vbuf[tid] = tanhf(acoef[t] * u);                      \
    }                                                                                \
    __syncthreads();                                                                 \
    if (tid == 255) flag_release(t);                                                 \
} while (0)

// ---------------- fused kernel ----------------
// CTA 0: sequential chain (produces g_u + flags).
// CTAs 1..2048: output tiles out[t, lb*128 .. lb*128+127, :], gated on g_flag[t].
__global__ void __launch_bounds__(256, 1) sstnn_fused(
    const float* __restrict__ x,         // (256,128)
    const float* __restrict__ pos_head,  // (1024,64) — only row 0 used
    const float* __restrict__ pos_tail,  // (1024,64) — only rows [0,256) used
    const float* __restrict__ W,         // (768,128,128) — only [0,256) used
    const float* __restrict__ a,         // (768,1024)
    float* __restrict__ out)             // (256,1024,128)
{
    extern __shared__ float sm[];
    const int tid = threadIdx.x;

    if (blockIdx.x != 0) {
        // ================= OUTPUT PATH =================
        const int idx = blockIdx.x - 1;
        const int t   = idx >> 3;
        const int lb  = idx & 7;

        if (tid == 0) {
            while (!flag_acquire(t)) __nanosleep(200);
        }
        __syncthreads();

        __shared__ float4 us[32];
        if (tid < 32) {
            const float4* up = (const float4*)g_u + t * 32 + tid;
            us[tid] = __ldcg(up);
        }
        __syncthreads();

        const int w = tid >> 5, lane = tid & 31;
        const float4 u4 = us[lane];
        const float* arow = a + (size_t)t * N_NEURONS + lb * 128;
        float4* op = (float4*)out + ((size_t)t * N_NEURONS + (size_t)lb * 128) * 32 + lane;

        #pragma unroll
        for (int it = 0; it < 16; it++) {
            const int l = (it << 3) + w;
            const float av = __ldg(arow + l);
            float4 r;
            r.x = tanha(av * u4.x);
            r.y = tanha(av * u4.y);
            r.z = tanha(av * u4.z);
            r.w = tanha(av * u4.w);
            __stcs(op + (size_t)l * 32, r);
        }
        return;
    }

    // ================= CHAIN PATH (CTA 0) =================
    float* vbuf  = sm + SMF_VBUF;
    float* part  = sm + SMF_PART;
    float* acoef = sm + SMF_ACOEF;
    const unsigned mbar_base = smem_u32(sm + SMF_MBAR);
    const int w = tid >> 5, lane = tid & 31;

    // ---- setup: v_0 + a-coefficient preload ----
    {
        // xsum partials
        const int jcol = tid & 127, h = tid >> 7;
        float s = 0.f;
        const float* xp = x + (size_t)(h * 128) * D_FEAT + jcol;
        #pragma unroll 8
        for (int i = 0; i < 128; i++) s += xp[(size_t)i * D_FEAT];
        part[tid] = s;

        // a-coefficient preload: acoef[t] = a[t, t+1] (strided gather, off chain path)
        if (tid < N_STEPS - 1) acoef[tid] = __ldg(a + (size_t)tid * N_NEURONS + (tid + 1));
        __syncthreads();

        // dsum partials
        const int d = tid & 63, q = tid >> 6;
        float sd = 0.f;
        const float* pp = pos_tail + (size_t)(q * 64) * 64 + d;
        #pragma unroll 8
        for (int r = 0; r < 64; r++) sd += pp[r * 64];
        part[256 + tid] = sd;
        __syncthreads();

        if (tid < 64) {
            float dv = part[256 + tid] + part[320 + tid] + part[384 + tid] + part[448 + tid];
            part[512 + tid] = dv * pos_head[tid];
        }
        __syncthreads();
        if (tid == 0) {
            float s0 = 0.f;
            #pragma unroll
            for (int dd = 0; dd < 64; dd++) s0 += part[512 + dd];
            part[576] = s0;
        }
        __syncthreads();
        if (tid < 128) vbuf[tid] = part[576] * (part[tid] + part[128 + tid]);
    }

    if (tid == 0) {
        for (int b = 0; b < NBUF; b++) mbar_init(mbar_base + 8u * b, 1);
    }
    __syncthreads();   // publishes v_0 and mbarrier init

    if (tid == 0) {
        for (int b = 0; b < NBUF; b++) {
            mbar_expect_tx(mbar_base + 8u * b, W_TILE * 4);
            tma_1d(smem_u32(sm + b * W_TILE), W + (size_t)b * W_TILE, W_TILE * 4,
                   mbar_base + 8u * b);
        }
    }

    // ---- prologue: W_0 into registers ----
    float4 RA[16], RB[16];
    mbar_wait(mbar_base, 0);
    {
        const float4* W0 = (const float4*)sm;
        #pragma unroll
        for (int r = 0; r < 16; r++) RA[r] = W0[((r << 3) + w) * 32 + lane];
    }

    // ---- main chain: 256 steps, register double-buffered ----
    for (int t = 0; t < N_STEPS; t += 2) {
        CHAIN_STEP(RA, RB, t);
        CHAIN_STEP(RB, RA, t + 1);
    }
}

// ---------------- launch ----------------
extern "C" void kernel_launch(void* const* d_in, const int* in_sizes, int n_in,
                              void* d_out, int out_size) {
    const float* x  = (const float*)d_in[0];
    const float* ph = (const float*)d_in[1];
    const float* pt = (const float*)d_in[2];
    const float* W  = (const float*)d_in[3];
    const float* a  = (const float*)d_in[4];

    cudaFuncSetAttribute(sstnn_fused, cudaFuncAttributeMaxDynamicSharedMemorySize, SMEM_BYTES);
    sstnn_fused<<<1 + N_STEPS * 8, 256, SMEM_BYTES>>>(x, ph, pt, W, a, (float*)d_out);
}

// round 4
// speedup vs baseline: 1.3915x; 1.3915x over previous
#include <cuda_runtime.h>
#include <cstdint>
#include <cstddef>

#define D_FEAT    128
#define N_STEPS   256          // O_SIZE: only first 256 scan steps feed the output
#define N_NEURONS 1024
#define W_TILE    (D_FEAT * D_FEAT)           // 16384 floats = 64 KB per step

// Scratch: u_t vectors produced by the chain, consumed by the output kernel.
__device__ __align__(16) float g_u[N_STEPS * D_FEAT];

__device__ __forceinline__ float tanha(float v) {
    float r;
    asm("tanh.approx.f32 %0, %1;" : "=f"(r) : "f"(v));
    return r;
}

// One chain step. RC holds W_t (registers); issues LDG for W_{t+1} into RN at the
// top so the loads have the whole step (~600cyc) to complete. vbuf: v_t -> v_{t+1}.
#define CHAIN_STEP(RC, RN, t) do {                                                   \
    if ((t) < N_STEPS - 1) {                                                         \
        const float4* Wn = (const float4*)W + (size_t)((t) + 1) * 4096 + thr_off;    \
        _Pragma("unroll")                                                            \
        for (int r = 0; r < 16; r++) RN[r] = __ldcs(Wn + (r << 8));                  \
    }                                                                                \
    float4 acc = make_float4(0.f, 0.f, 0.f, 0.f);                                    \
    _Pragma("unroll")                                                                \
    for (int r = 0; r < 16; r++) {                                                   \
        const float vj = vbuf[(r << 3) + w];                                         \
        acc.x += vj * RC[r].x; acc.y += vj * RC[r].y;                                \
        acc.z += vj * RC[r].z; acc.w += vj * RC[r].w;                                \
    }                                                                                \
    ((float4*)part)[(w << 5) + lane] = acc;                                          \
    __syncthreads();                                                                 \
    if (tid < 128) {                                                                 \
        float u = part[tid]       + part[128 + tid] + part[256 + tid]                \
                + part[384 + tid] + part[512 + tid] + part[640 + tid]                \
                + part[768 + tid] + part[896 + tid];                                 \
        __stcg(&g_u[(t) * 128 + tid], u);                                            \
        if ((t) < N_STEPS - 1) vbuf[tid] = tanhf(acoef[t] * u);                      \
    }                                                                                \
    __syncthreads();                                                                 \
} while (0)

// ---------------- Phase A: sequential chain (single CTA) ----------------
// v_0[j] = (pos_head[0]·dsum) * xsum[j];  u_t = v_t @ W[t];  v_{t+1} = tanh(a[t,t+1]*u_t)
// W streamed GMEM -> registers (LDG.128), 2-deep register pipeline. No smem staging:
// avoids the TMA-write + LDS-read crossbar contention (shared 128B/cyc port).
__global__ void __launch_bounds__(256, 1) chain_kernel(
    const float* __restrict__ x,         // (256,128)
    const float* __restrict__ pos_head,  // (1024,64) — only row 0 used
    const float* __restrict__ pos_tail,  // (1024,64) — only rows [0,256) used
    const float* __restrict__ W,         // (768,128,128) — only [0,256) used
    const float* __restrict__ a)         // (768,1024)
{
    __shared__ float vbuf[128];
    __shared__ float part[1024];
    __shared__ float acoef[N_STEPS];

    const int tid  = threadIdx.x;
    const int w    = tid >> 5;
    const int lane = tid & 31;
    // thread's float4 offset inside one 128x128 W tile: row j=(r<<3)+w, k-chunk=lane
    const int thr_off = (w << 5) + lane;   // + (r<<8) per r

    // ---- setup: v_0 + a-coefficient preload (off the serial path) ----
    {
        const int jcol = tid & 127, h = tid >> 7;
        float s = 0.f;
        const float* xp = x + (size_t)(h * 128) * D_FEAT + jcol;
        #pragma unroll 8
        for (int i = 0; i < 128; i++) s += xp[(size_t)i * D_FEAT];
        part[tid] = s;

        if (tid < N_STEPS - 1) acoef[tid] = __ldg(a + (size_t)tid * N_NEURONS + (tid + 1));
        __syncthreads();

        const int d = tid & 63, q = tid >> 6;
        float sd = 0.f;
        const float* pp = pos_tail + (size_t)(q * 64) * 64 + d;
        #pragma unroll 8
        for (int r = 0; r < 64; r++) sd += pp[r * 64];
        part[256 + tid] = sd;   // careful: reuses part[256..511]; xsum lives in [0,256)
        __syncthreads();

        if (tid < 64) {
            float dv = part[256 + tid] + part[320 + tid] + part[384 + tid] + part[448 + tid];
            part[512 + tid] = dv * pos_head[tid];
        }
        __syncthreads();
        if (tid == 0) {
            float s0 = 0.f;
            #pragma unroll
            for (int dd = 0; dd < 64; dd++) s0 += part[512 + dd];
            part[576] = s0;
        }
        __syncthreads();
        if (tid < 128) vbuf[tid] = part[576] * (part[tid] + part[128 + tid]);
        __syncthreads();
    }

    // ---- prologue: W_0 into registers ----
    float4 RA[16], RB[16];
    {
        const float4* W0 = (const float4*)W + thr_off;
        #pragma unroll
        for (int r = 0; r < 16; r++) RA[r] = __ldcs(W0 + (r << 8));
    }

    // ---- main chain: 256 steps, register double-buffered ----
    for (int t = 0; t < N_STEPS; t += 2) {
        CHAIN_STEP(RA, RB, t);
        CHAIN_STEP(RB, RA, t + 1);
    }
}

// ---------------- Phase B: output generation (full chip, DRAM-write bound) ----------------
// out[t, l, j] = tanh(a[t, l] * u_t[j]);  grid = 256 t-values x 8 l-blocks of 128 rows.
__global__ void __launch_bounds__(256) out_kernel(const float* __restrict__ a,
                                                  float* __restrict__ out)
{
    __shared__ float4 us[32];
    __shared__ float as[128];
    const int t  = blockIdx.x >> 3;
    const int lb = blockIdx.x & 7;
    const int tid = threadIdx.x;

    if (tid < 32) us[tid] = __ldcg((const float4*)g_u + t * 32 + tid);
    if (tid >= 128) as[tid - 128] = __ldg(a + (size_t)t * N_NEURONS + lb * 128 + (tid - 128));
    __syncthreads();

    const int w = tid >> 5, lane = tid & 31;
    const float4 u4 = us[lane];                       // lane's 4 j-columns, reused 16x
    float4* op = (float4*)out + ((size_t)t * N_NEURONS + (size_t)lb * 128) * 32 + lane;

    #pragma unroll
    for (int it = 0; it < 16; it++) {
        const int l = (it << 3) + w;
        const float av = as[l];                       // warp-uniform smem broadcast
        float4 r;
        r.x = tanha(av * u4.x);
        r.y = tanha(av * u4.y);
        r.z = tanha(av * u4.z);
        r.w = tanha(av * u4.w);
        __stcs(op + (size_t)l * 32, r);               // streaming store, 512B/warp coalesced
    }
}

// ---------------- launch ----------------
extern "C" void kernel_launch(void* const* d_in, const int* in_sizes, int n_in,
                              void* d_out, int out_size) {
    const float* x  = (const float*)d_in[0];
    const float* ph = (const float*)d_in[1];
    const float* pt = (const float*)d_in[2];
    const float* W  = (const float*)d_in[3];
    const float* a  = (const float*)d_in[4];

    chain_kernel<<<1, 256>>>(x, ph, pt, W, a);
    out_kernel<<<N_STEPS * 8, 256>>>(a, (float*)d_out);
}

// round 5
// speedup vs baseline: 1.8253x; 1.3117x over previous
#include <cuda_runtime.h>
#include <cstdint>
#include <cstddef>

#define D_FEAT    128
#define N_STEPS   256          // O_SIZE: only first 256 scan steps feed the output
#define N_NEURONS 1024
#define W_TILE    (D_FEAT * D_FEAT)           // 16384 floats = 64 KB per step
#define NBUF      3

// smem layout (floats): Wbuf[3] | vbuf 128 | part 1024 | acoef 256 | mbars(3x8B)
#define SMF_VBUF    (NBUF * W_TILE)
#define SMF_PART    (SMF_VBUF + 128)
#define SMF_ACOEF   (SMF_PART + 1024)
#define SMF_MBAR    (SMF_ACOEF + 256)         // float index; *4 is 8B-aligned
#define SMEM_FLOATS (SMF_MBAR + 8)
#define SMEM_BYTES  (SMEM_FLOATS * 4)

// Scratch: u_t vectors produced by the chain, consumed by the output kernel.
__device__ __align__(16) float g_u[N_STEPS * D_FEAT];

// ---------------- PTX helpers ----------------
__device__ __forceinline__ unsigned smem_u32(const void* p) {
    unsigned r;
    asm("{ .reg .u64 t; cvta.to.shared.u64 t, %1; cvt.u32.u64 %0, t; }" : "=r"(r) : "l"(p));
    return r;
}
__device__ __forceinline__ void mbar_init(unsigned m, unsigned cnt) {
    asm volatile("mbarrier.init.shared.b64 [%0], %1;" :: "r"(m), "r"(cnt) : "memory");
}
__device__ __forceinline__ void mbar_expect_tx(unsigned m, unsigned bytes) {
    asm volatile("mbarrier.arrive.expect_tx.shared.b64 _, [%0], %1;" :: "r"(m), "r"(bytes) : "memory");
}
__device__ __forceinline__ void mbar_wait(unsigned m, unsigned parity) {
    asm volatile(
        "{\n\t"
        ".reg .pred P1;\n\t"
        "WL_%=:\n\t"
        "mbarrier.try_wait.parity.acquire.cta.shared::cta.b64 P1, [%0], %1, 0x989680;\n\t"
        "@P1 bra.uni WD_%=;\n\t"
        "bra.uni WL_%=;\n\t"
        "WD_%=:\n\t"
        "}"
        :: "r"(m), "r"(parity) : "memory");
}
__device__ __forceinline__ void tma_1d(unsigned dst, const void* src, unsigned bytes, unsigned m) {
    asm volatile(
        "cp.async.bulk.shared::cta.global.mbarrier::complete_tx::bytes [%0], [%1], %2, [%3];"
        :: "r"(dst), "l"(src), "r"(bytes), "r"(m) : "memory");
}
__device__ __forceinline__ float tanha(float v) {
    float r;
    asm("tanh.approx.f32 %0, %1;" : "=f"(r) : "f"(v));
    return r;
}

// ---------------- Phase A: sequential chain (single CTA) ----------------
// v_0[j] = (pos_head[0]·dsum) * xsum[j];  u_t = v_t @ W[t];  v_{t+1} = tanh(a[t,t+1]*u_t)
// W streamed via 1-D bulk TMA into a 3-deep smem ring; FFMAs read W straight from
// smem (LDS.128 @ 128B/cyc crossbar — avoids the ~2x L1tex wavefront replay tax
// that the GMEM->register LDG.128 path pays).
__global__ void __launch_bounds__(256, 1) chain_kernel(
    const float* __restrict__ x,         // (256,128)
    const float* __restrict__ pos_head,  // (1024,64) — only row 0 used
    const float* __restrict__ pos_tail,  // (1024,64) — only rows [0,256) used
    const float* __restrict__ W,         // (768,128,128) — only [0,256) used
    const float* __restrict__ a)         // (768,1024)
{
    extern __shared__ float sm[];
    float* vbuf  = sm + SMF_VBUF;
    float* part  = sm + SMF_PART;
    float* acoef = sm + SMF_ACOEF;
    const unsigned mbar_base = smem_u32(sm + SMF_MBAR);

    const int tid  = threadIdx.x;
    const int w    = tid >> 5;
    const int lane = tid & 31;

    // ---- setup: v_0 + a-coefficient preload (off the serial path) ----
    {
        const int jcol = tid & 127, h = tid >> 7;
        float s = 0.f;
        const float* xp = x + (size_t)(h * 128) * D_FEAT + jcol;
        #pragma unroll 8
        for (int i = 0; i < 128; i++) s += xp[(size_t)i * D_FEAT];
        part[tid] = s;

        if (tid < N_STEPS - 1) acoef[tid] = __ldg(a + (size_t)tid * N_NEURONS + (tid + 1));
        __syncthreads();

        const int d = tid & 63, q = tid >> 6;
        float sd = 0.f;
        const float* pp = pos_tail + (size_t)(q * 64) * 64 + d;
        #pragma unroll 8
        for (int r = 0; r < 64; r++) sd += pp[r * 64];
        part[256 + tid] = sd;
        __syncthreads();

        if (tid < 64) {
            float dv = part[256 + tid] + part[320 + tid] + part[384 + tid] + part[448 + tid];
            part[512 + tid] = dv * pos_head[tid];
        }
        __syncthreads();
        if (tid == 0) {
            float s0 = 0.f;
            #pragma unroll
            for (int dd = 0; dd < 64; dd++) s0 += part[512 + dd];
            part[576] = s0;
        }
        __syncthreads();
        if (tid < 128) vbuf[tid] = part[576] * (part[tid] + part[128 + tid]);
    }

    if (tid == 0) {
        #pragma unroll
        for (int b = 0; b < NBUF; b++) mbar_init(mbar_base + 8u * b, 1);
    }
    __syncthreads();   // publishes v_0 + mbarrier init before first TMA

    if (tid == 0) {
        #pragma unroll
        for (int b = 0; b < NBUF; b++) {
            mbar_expect_tx(mbar_base + 8u * b, W_TILE * 4);
            tma_1d(smem_u32(sm + b * W_TILE), W + (size_t)b * W_TILE, W_TILE * 4,
                   mbar_base + 8u * b);
        }
    }

    // ---- main chain ----
    for (int t = 0; t < N_STEPS; t++) {
        const int      buf = t % NBUF;
        const unsigned mb  = mbar_base + 8u * buf;
        mbar_wait(mb, (t / NBUF) & 1);

        // Matvec partials straight from smem: warp w rows j=w,8+w,...; lane k-chunk [4*lane,+4)
        const float4* W4 = (const float4*)(sm + buf * W_TILE);
        float4 acc = make_float4(0.f, 0.f, 0.f, 0.f);
        #pragma unroll
        for (int r = 0; r < 16; r++) {
            const int j = (r << 3) + w;
            const float vj = vbuf[j];                 // warp-uniform broadcast
            const float4 wv = W4[j * 32 + lane];      // conflict-free LDS.128
            acc.x += vj * wv.x; acc.y += vj * wv.y;
            acc.z += vj * wv.z; acc.w += vj * wv.w;
        }
        ((float4*)part)[(w << 5) + lane] = acc;
        __syncthreads();                              // buffer reads complete here

        // Refill this buffer for step t+3 — async write overlaps tail + next FFMAs.
        if (tid == 0 && t + NBUF < N_STEPS) {
            mbar_expect_tx(mb, W_TILE * 4);
            tma_1d(smem_u32(sm + buf * W_TILE), W + (size_t)(t + NBUF) * W_TILE,
                   W_TILE * 4, mb);
        }

        if (tid < 128) {   // thread k reduces the 8 warp partials
            float u = part[tid]       + part[128 + tid] + part[256 + tid]
                    + part[384 + tid] + part[512 + tid] + part[640 + tid]
                    + part[768 + tid] + part[896 + tid];
            __stcg(&g_u[t * 128 + tid], u);
            if (t < N_STEPS - 1) vbuf[tid] = tanhf(acoef[t] * u);  // accurate: feeds forward
        }
        __syncthreads();
    }
}

// ---------------- Phase B: output generation (full chip, DRAM-write bound) ----------------
// out[t, l, j] = tanh(a[t, l] * u_t[j]);  grid = 256 t-values x 8 l-blocks of 128 rows.
__global__ void __launch_bounds__(256) out_kernel(const float* __restrict__ a,
                                                  float* __restrict__ out)
{
    __shared__ float4 us[32];
    __shared__ float as[128];
    const int t  = blockIdx.x >> 3;
    const int lb = blockIdx.x & 7;
    const int tid = threadIdx.x;

    if (tid < 32) us[tid] = __ldcg((const float4*)g_u + t * 32 + tid);
    if (tid >= 128) as[tid - 128] = __ldg(a + (size_t)t * N_NEURONS + lb * 128 + (tid - 128));
    __syncthreads();

    const int w = tid >> 5, lane = tid & 31;
    const float4 u4 = us[lane];                       // lane's 4 j-columns, reused 16x
    float4* op = (float4*)out + ((size_t)t * N_NEURONS + (size_t)lb * 128) * 32 + lane;

    #pragma unroll
    for (int it = 0; it < 16; it++) {
        const int l = (it << 3) + w;
        const float av = as[l];                       // warp-uniform smem broadcast
        float4 r;
        r.x = tanha(av * u4.x);
        r.y = tanha(av * u4.y);
        r.z = tanha(av * u4.z);
        r.w = tanha(av * u4.w);
        __stcs(op + (size_t)l * 32, r);               // streaming store, 512B/warp coalesced
    }
}

// ---------------- launch ----------------
extern "C" void kernel_launch(void* const* d_in, const int* in_sizes, int n_in,
                              void* d_out, int out_size) {
    const float* x  = (const float*)d_in[0];
    const float* ph = (const float*)d_in[1];
    const float* pt = (const float*)d_in[2];
    const float* W  = (const float*)d_in[3];
    const float* a  = (const float*)d_in[4];

    cudaFuncSetAttribute(chain_kernel, cudaFuncAttributeMaxDynamicSharedMemorySize, SMEM_BYTES);
    chain_kernel<<<1, 256, SMEM_BYTES>>>(x, ph, pt, W, a);
    out_kernel<<<N_STEPS * 8, 256>>>(a, (float*)d_out);
}